// round 1
// baseline (speedup 1.0000x reference)
#include <cuda_runtime.h>
#include <cuda_bf16.h>

// DegeneratePool: out = x / (224*224 + 1e-9)  -> elementwise scale.
// N = 32*64*224*224 = 102,760,448 floats, divisible by 4.
// Pure HBM-bound streaming kernel: float4 in, float4 out.

__global__ void __launch_bounds__(256)
scale_kernel_v4(const float4* __restrict__ in, float4* __restrict__ out,
                float scale, long long n4) {
    long long i = (long long)blockIdx.x * blockDim.x + threadIdx.x;
    if (i < n4) {
        float4 v = in[i];
        v.x *= scale;
        v.y *= scale;
        v.z *= scale;
        v.w *= scale;
        out[i] = v;
    }
}

// Fallback for any tail elements not covered by float4 (not needed for this
// shape, but keeps the launcher shape-agnostic and correct).
__global__ void scale_kernel_tail(const float* __restrict__ in,
                                  float* __restrict__ out,
                                  float scale, long long start, long long n) {
    long long i = start + (long long)blockIdx.x * blockDim.x + threadIdx.x;
    if (i < n) {
        out[i] = in[i] * scale;
    }
}

extern "C" void kernel_launch(void* const* d_in, const int* in_sizes, int n_in,
                              void* d_out, int out_size) {
    const float* x = (const float*)d_in[0];
    float* out = (float*)d_out;
    long long n = (long long)in_sizes[0];

    // H*W = 224*224 = 50176; divisor = 50176 + 1e-9.
    const double divisor = 50176.0 + 1e-9;
    const float scale = (float)(1.0 / divisor);

    long long n4 = n / 4;
    if (n4 > 0) {
        int threads = 256;
        long long blocks = (n4 + threads - 1) / threads;
        scale_kernel_v4<<<(unsigned int)blocks, threads>>>(
            (const float4*)x, (float4*)out, scale, n4);
    }
    long long tail_start = n4 * 4;
    long long tail = n - tail_start;
    if (tail > 0) {
        int threads = 256;
        long long blocks = (tail + threads - 1) / threads;
        scale_kernel_tail<<<(unsigned int)blocks, threads>>>(
            x, out, scale, tail_start, n);
    }
}

// round 2
// speedup vs baseline: 1.0130x; 1.0130x over previous
#include <cuda_runtime.h>
#include <cuda_bf16.h>

// DegeneratePool: out = x * (1 / (224*224 + 1e-9))  -> elementwise scale.
// N = 32*64*224*224 = 102,760,448 floats (divisible by 4096).
// HBM-bound streaming kernel. v2: MLP=4 per thread (4 block-strided float4s)
// + streaming cache hints (__ldcs/__stcs) to keep dead lines out of L2.

#define TPB 256
#define VPT 4  // float4s per thread

__global__ void __launch_bounds__(TPB)
scale_kernel_v4x4(const float4* __restrict__ in, float4* __restrict__ out,
                  float scale, long long n4) {
    long long base = (long long)blockIdx.x * (TPB * VPT) + threadIdx.x;

    // Fast path: whole tile in range (true for every block at this shape).
    if (base + (VPT - 1) * TPB < n4) {
        float4 v0 = __ldcs(&in[base + 0 * TPB]);
        float4 v1 = __ldcs(&in[base + 1 * TPB]);
        float4 v2 = __ldcs(&in[base + 2 * TPB]);
        float4 v3 = __ldcs(&in[base + 3 * TPB]);
        v0.x *= scale; v0.y *= scale; v0.z *= scale; v0.w *= scale;
        v1.x *= scale; v1.y *= scale; v1.z *= scale; v1.w *= scale;
        v2.x *= scale; v2.y *= scale; v2.z *= scale; v2.w *= scale;
        v3.x *= scale; v3.y *= scale; v3.z *= scale; v3.w *= scale;
        __stcs(&out[base + 0 * TPB], v0);
        __stcs(&out[base + 1 * TPB], v1);
        __stcs(&out[base + 2 * TPB], v2);
        __stcs(&out[base + 3 * TPB], v3);
    } else {
        #pragma unroll
        for (int k = 0; k < VPT; k++) {
            long long i = base + (long long)k * TPB;
            if (i < n4) {
                float4 v = __ldcs(&in[i]);
                v.x *= scale; v.y *= scale; v.z *= scale; v.w *= scale;
                __stcs(&out[i], v);
            }
        }
    }
}

// Tail for n not divisible by 4 (not hit at this shape; keeps launcher general).
__global__ void scale_kernel_tail(const float* __restrict__ in,
                                  float* __restrict__ out,
                                  float scale, long long start, long long n) {
    long long i = start + (long long)blockIdx.x * blockDim.x + threadIdx.x;
    if (i < n) {
        out[i] = in[i] * scale;
    }
}

extern "C" void kernel_launch(void* const* d_in, const int* in_sizes, int n_in,
                              void* d_out, int out_size) {
    const float* x = (const float*)d_in[0];
    float* out = (float*)d_out;
    long long n = (long long)in_sizes[0];

    const double divisor = 50176.0 + 1e-9;  // 224*224 + eps
    const float scale = (float)(1.0 / divisor);

    long long n4 = n / 4;
    if (n4 > 0) {
        long long tile = (long long)TPB * VPT;
        long long blocks = (n4 + tile - 1) / tile;
        scale_kernel_v4x4<<<(unsigned int)blocks, TPB>>>(
            (const float4*)x, (float4*)out, scale, n4);
    }
    long long tail_start = n4 * 4;
    long long tail = n - tail_start;
    if (tail > 0) {
        long long blocks = (tail + TPB - 1) / TPB;
        scale_kernel_tail<<<(unsigned int)blocks, TPB>>>(
            x, out, scale, tail_start, n);
    }
}